// round 10
// baseline (speedup 1.0000x reference)
#include <cuda_runtime.h>

#define CCH 512
#define TT  8192
#define PLANE (TT * CCH)

typedef unsigned long long u64;

__device__ __forceinline__ u64 fma2(u64 a, u64 b, u64 c) {
    u64 d; asm("fma.rn.f32x2 %0, %1, %2, %3;" : "=l"(d) : "l"(a), "l"(b), "l"(c)); return d;
}
__device__ __forceinline__ u64 mul2(u64 a, u64 b) {
    u64 d; asm("mul.rn.f32x2 %0, %1, %2;" : "=l"(d) : "l"(a), "l"(b)); return d;
}
__device__ __forceinline__ u64 add2(u64 a, u64 b) {
    u64 d; asm("add.rn.f32x2 %0, %1, %2;" : "=l"(d) : "l"(a), "l"(b)); return d;
}
__device__ __forceinline__ u64 pack2(float lo, float hi) {
    u64 d; asm("mov.b64 %0, {%1, %2};" : "=l"(d) : "f"(lo), "f"(hi)); return d;
}
__device__ __forceinline__ float2 unpack2(u64 a) {
    float2 r; asm("mov.b64 {%0, %1}, %2;" : "=f"(r.x), "=f"(r.y) : "l"(a)); return r;
}

// ---- static device scratch ----
__device__ float g_U[TT * 16];        // U[t,j] = b1[j] + W1^T y_t
__device__ float g_invd[TT];          // rsqrt(s_t)
__device__ u64   g_KVu[5 * PLANE];    // plane 0:(k0,k1) 1:(k2,k3) 2:(v0,v1) 3:(v2,v3) 4:(k4,v4); [m][t][c]
__device__ float g_dotT[PLANE];       // raw dot, t-major [t][c]

// ---------------- repack K,V ----------------
__global__ void repack_kv(const float* __restrict__ K, const float* __restrict__ V)
{
    const int idx = blockIdx.x * blockDim.x + threadIdx.x;   // t*512 + c
    const long b = (long)idx * 5;
    g_KVu[0 * PLANE + idx] = pack2(K[b + 0], K[b + 1]);
    g_KVu[1 * PLANE + idx] = pack2(K[b + 2], K[b + 3]);
    g_KVu[2 * PLANE + idx] = pack2(V[b + 0], V[b + 1]);
    g_KVu[3 * PLANE + idx] = pack2(V[b + 2], V[b + 3]);
    g_KVu[4 * PLANE + idx] = pack2(K[b + 4], V[b + 4]);
}

// ---------------- precompute U ----------------
__global__ void precompute_U(const float* __restrict__ y,
                             const float* __restrict__ W1,
                             const float* __restrict__ b1)
{
    const int j  = threadIdx.x & 15;
    const int t4 = blockIdx.x * 32 + (threadIdx.x >> 4);
    const int t0 = t4 * 4;
    const float bj = b1[j];
    float a0 = bj, a1 = bj, a2 = bj, a3 = bj;
#pragma unroll 8
    for (int c = 0; c < CCH; c++) {
        const float4 yv = *(const float4*)&y[c * TT + t0];
        const float w = W1[c * 16 + j];
        a0 = fmaf(yv.x, w, a0);
        a1 = fmaf(yv.y, w, a1);
        a2 = fmaf(yv.z, w, a2);
        a3 = fmaf(yv.w, w, a3);
    }
    g_U[(t0 + 0) * 16 + j] = a0;
    g_U[(t0 + 1) * 16 + j] = a1;
    g_U[(t0 + 2) * 16 + j] = a2;
    g_U[(t0 + 3) * 16 + j] = a3;
}

// ---------------- sequential recurrence, 1 CTA, 512 threads ----------------
// sdot: interleaved u64 channel pairs: word 2*c2+(c>>8) holds dot[c];
//       u64 slot c2 = (dot[c2], dot[c2+256]).
// B (warps 0-7 only): warp w reduces j=2w,2w+1 via packed fma2 over 256 pairs;
//       s-chain interleaved; lane0 writes sh2[w] = (h_{2w}, h_{2w+1}).
// C (all warps): q via 8 fma2 over sh2 pairs.
// A (all warps): packed ema/dot/sp; interleaved STS of dot; sp 5-round chain.
__global__ __launch_bounds__(512, 1)
void rca_kernel(const float* __restrict__ W1,
                const float* __restrict__ W2,
                const float* __restrict__ b2)
{
    __shared__ __align__(16) u64 sdot[256];   // channel-pair dots
    __shared__ __align__(16) u64 sh2[8];      // (h_{2w}, h_{2w+1})
    __shared__ float ss[16];

    const int tid  = threadIdx.x;
    const int wid  = tid >> 5;
    const int lane = tid & 31;

    // --- B-phase packed W1 (reducer warps w<8; all threads load to keep code uniform) ---
    // f = lane + 32*ii indexes the float4 read: covers channel-pairs 2f, 2f+1.
    const int jA = 2 * (wid & 7), jB = jA + 1;
    u64 w1A[8], w1B[8];
#pragma unroll
    for (int ii = 0; ii < 4; ii++) {
        const int f = lane + 32 * ii;
        w1A[2 * ii + 0] = pack2(W1[(2 * f) * 16 + jA],     W1[(2 * f + 256) * 16 + jA]);
        w1A[2 * ii + 1] = pack2(W1[(2 * f + 1) * 16 + jA], W1[(2 * f + 257) * 16 + jA]);
        w1B[2 * ii + 0] = pack2(W1[(2 * f) * 16 + jB],     W1[(2 * f + 256) * 16 + jB]);
        w1B[2 * ii + 1] = pack2(W1[(2 * f + 1) * 16 + jB], W1[(2 * f + 257) * 16 + jB]);
    }

    // --- C-phase packed W2: w2p[w] = (W2[2w][c], W2[2w+1][c]) ---
    u64 w2p[8];
#pragma unroll
    for (int w = 0; w < 8; w++)
        w2p[w] = pack2(W2[(2 * w) * CCH + tid], W2[(2 * w + 1) * CCH + tid]);
    const float b2c = b2[tid];

    const u64 c95 = pack2(0.95f, 0.95f);
    u64 e01 = 0, e23 = 0;
    float e4 = 0.f;

    // depth-2 prefetch
    u64  kv[2][5];
    float uA[2], uB[2];
#pragma unroll
    for (int i = 0; i < 2; i++) {
        const int idx = i * CCH + tid;
#pragma unroll
        for (int m = 0; m < 5; m++) kv[i][m] = g_KVu[m * PLANE + idx];
        uA[i] = g_U[i * 16 + jA];
        uB[i] = g_U[i * 16 + jB];
    }

    // interleaved sdot address for this thread's channel
    const int sd_addr = 2 * (tid & 255) + (tid >> 8);
    float* sdotf = (float*)sdot;

    sdot[tid & 255] = 0;
    if (tid < 16) ss[tid] = 0.f;
    __syncthreads();

    const ulonglong2* sd2 = (const ulonglong2*)sdot;
    const ulonglong2* sh4 = (const ulonglong2*)sh2;

    for (int t0 = 0; t0 < TT + 2; t0 += 2) {
#pragma unroll
        for (int i = 0; i < 2; i++) {
            const int t = t0 + i;

            // ---------- B: warps 0-7 reduce g[2w], g[2w+1]; s from ss ----------
            if (wid < 8) {
                u64 aA0 = 0, aA1 = 0, aB0 = 0, aB1 = 0;
#pragma unroll
                for (int ii = 0; ii < 4; ii++) {
                    const ulonglong2 d = sd2[lane + 32 * ii];
                    aA0 = fma2(d.x, w1A[2 * ii + 0], aA0);
                    aA1 = fma2(d.y, w1A[2 * ii + 1], aA1);
                    aB0 = fma2(d.x, w1B[2 * ii + 0], aB0);
                    aB1 = fma2(d.y, w1B[2 * ii + 1], aB1);
                }
                const float2 fA = unpack2(add2(aA0, aA1));
                const float2 fB = unpack2(add2(aB0, aB1));
                float gA = fA.x + fA.y;
                float gB = fB.x + fB.y;
                float s = ss[lane & 15];
                // interleaved chains: gA(5), gB(5), s(4)
                gA += __shfl_xor_sync(0xffffffffu, gA, 16);
                gB += __shfl_xor_sync(0xffffffffu, gB, 16);
                s  += __shfl_xor_sync(0xffffffffu, s, 8);
                gA += __shfl_xor_sync(0xffffffffu, gA, 8);
                gB += __shfl_xor_sync(0xffffffffu, gB, 8);
                s  += __shfl_xor_sync(0xffffffffu, s, 4);
                gA += __shfl_xor_sync(0xffffffffu, gA, 4);
                gB += __shfl_xor_sync(0xffffffffu, gB, 4);
                s  += __shfl_xor_sync(0xffffffffu, s, 2);
                gA += __shfl_xor_sync(0xffffffffu, gA, 2);
                gB += __shfl_xor_sync(0xffffffffu, gB, 2);
                s  += __shfl_xor_sync(0xffffffffu, s, 1);
                gA += __shfl_xor_sync(0xffffffffu, gA, 1);
                gB += __shfl_xor_sync(0xffffffffu, gB, 1);

                const float inv = rsqrtf(fmaxf(s, 1e-37f));
                if (lane == 0) {
                    const float hA = fmaxf(fmaf(gA, inv, uA[i]), 0.f);
                    const float hB = fmaxf(fmaf(gB, inv, uB[i]), 0.f);
                    sh2[wid] = pack2(hA, hB);
                    if (wid == 0 && t > 0) g_invd[t - 1] = inv;
                }
            }
            if (t == TT) return;

            __syncthreads();   // sh2 visible; sdot/ss reads done before A writes

            // ---------- C: q = b2 + sum_w (h2w,h2w+1).(W2 pair) ----------
            u64 q0 = 0, q1 = 0, q2 = 0, q3 = 0;
#pragma unroll
            for (int w = 0; w < 8; w += 4) {
                const ulonglong2 hp0 = sh4[(w >> 1) + 0];
                const ulonglong2 hp1 = sh4[(w >> 1) + 1];
                q0 = fma2(hp0.x, w2p[w + 0], q0);
                q1 = fma2(hp0.y, w2p[w + 1], q1);
                q2 = fma2(hp1.x, w2p[w + 2], q2);
                q3 = fma2(hp1.y, w2p[w + 3], q3);
            }
            const float2 qf = unpack2(add2(add2(q0, q1), add2(q2, q3)));
            const float qm = 0.05f * (b2c + qf.x + qf.y);

            // ---------- A: packed ema, dot, sp ----------
            const u64 qm2 = pack2(qm, qm);
            e01 = fma2(e01, c95, mul2(kv[i][0], qm2));
            e23 = fma2(e23, c95, mul2(kv[i][1], qm2));
            const float2 k4v4 = unpack2(kv[i][4]);
            e4 = fmaf(0.95f, e4, qm * k4v4.x);

            u64 d2 = mul2(e01, kv[i][2]);
            d2 = fma2(e23, kv[i][3], d2);
            const float2 dd = unpack2(d2);
            float dot = dd.x + dd.y;
            dot = fmaf(e4, k4v4.y, dot);

            u64 s2 = mul2(e01, e01);
            s2 = fma2(e23, e23, s2);
            const float2 sv = unpack2(s2);
            float sp = sv.x + sv.y;
            sp = fmaf(e4, e4, sp);

            sdotf[sd_addr] = dot;          // interleaved pair layout
            g_dotT[t * CCH + tid] = dot;   // coalesced raw store

            // prefetch t+2 into this slot
            {
                const int tn  = (t + 2 < TT) ? (t + 2) : (TT - 1);
                const int idx = tn * CCH + tid;
#pragma unroll
                for (int m = 0; m < 5; m++) kv[i][m] = g_KVu[m * PLANE + idx];
                uA[i] = g_U[tn * 16 + jA];
                uB[i] = g_U[tn * 16 + jB];
            }

            // warp-reduce sp -> ss[wid]
            sp += __shfl_xor_sync(0xffffffffu, sp, 16);
            sp += __shfl_xor_sync(0xffffffffu, sp, 8);
            sp += __shfl_xor_sync(0xffffffffu, sp, 4);
            sp += __shfl_xor_sync(0xffffffffu, sp, 2);
            sp += __shfl_xor_sync(0xffffffffu, sp, 1);
            if (lane == 0) ss[wid] = sp;

            __syncthreads();   // sdot/ss visible for next B
        }
    }
}

// ---------------- transpose + scale: out[c*TT+t] = dotT[t][c] * invd[t] ----------------
__global__ void transpose_scale(float* __restrict__ out)
{
    __shared__ float tile[32][33];
    const int t0 = blockIdx.x * 32;
    const int c0 = blockIdx.y * 32;
    const int tx = threadIdx.x;
    const int ty = threadIdx.y;

#pragma unroll
    for (int r = ty; r < 32; r += 8)
        tile[r][tx] = g_dotT[(t0 + r) * CCH + (c0 + tx)] * g_invd[t0 + r];
    __syncthreads();
#pragma unroll
    for (int r = ty; r < 32; r += 8)
        out[(long)(c0 + r) * TT + (t0 + tx)] = tile[tx][r];
}

extern "C" void kernel_launch(void* const* d_in, const int* in_sizes, int n_in,
                              void* d_out, int out_size) {
    const float* y  = (const float*)d_in[0];
    const float* Kp = (const float*)d_in[1];
    const float* Vp = (const float*)d_in[2];
    const float* W1 = (const float*)d_in[3];
    const float* b1 = (const float*)d_in[4];
    const float* W2 = (const float*)d_in[5];
    const float* b2 = (const float*)d_in[6];
    float* out = (float*)d_out;

    repack_kv<<<PLANE / 256, 256>>>(Kp, Vp);
    precompute_U<<<TT / 128, 512>>>(y, W1, b1);
    rca_kernel<<<1, 512>>>(W1, W2, b2);
    dim3 tb(32, 8);
    dim3 tg(TT / 32, CCH / 32);
    transpose_scale<<<tg, tb>>>(out);
}